// round 12
// baseline (speedup 1.0000x reference)
#include <cuda_runtime.h>
#include <cuda_fp16.h>
#include <cstdint>

// ============================================================================
// MoEGate via mma.sync m16n8k16 fp16 2-term split (3 passes, scaled residuals)
// Round 12: round-11 split-K shape + software-pipelined fragments
//   - 6-slot stage ring, 2 chunks per barrier, wait_group(1)
//   - x LDS for c+1 issued before MMAs of c; cvt after MMAs (off critical path)
// out fp32: [0,32768) indices, [32768,65536) weights, [65536] aux_loss
// ============================================================================

#define N_TOKENS 16384
#define DDIM     2048
#define NEXP     64
#define M_CTA    64
#define NCTA     (N_TOKENS / M_CTA)   // 256
#define NCHUNK   (DDIM / 32)          // 64 chunks of K=32
#define S_LEN    4096
#define NBATCH   4
#define CTA_PER_BATCH (NCTA / NBATCH) // 64
#define RSCALE   4096.0f
#define INV_RS   (1.0f / 4096.0f)

// smem: 6 stages of [x: 64 rows x 36 floats][w: 512 uint4]
#define XS_STRIDE   36
#define XS_BYTES    (M_CTA * XS_STRIDE * 4)   // 9216
#define WS_BYTES    (512 * 16)                // 8192
#define STG_SIZE    (XS_BYTES + WS_BYTES)     // 17408
#define NSTAGE      6
#define SMEM_BYTES  (NSTAGE * STG_SIZE)       // 104448
#define SC_STRIDE   66

// device scratch
__device__ uint4    g_wpk[NCHUNK * 512];      // fragment-packed W (h1 | h2*4096)
__device__ float    g_cnt[NCTA * NEXP];
__device__ float    g_sum[NCTA * NEXP];
__device__ unsigned g_ticket;

// ---------------------------------------------------------------------------
__device__ __forceinline__ uint32_t smem_u32(const void* p) {
    uint32_t a;
    asm("{ .reg .u64 t; cvta.to.shared.u64 t, %1; cvt.u32.u64 %0, t; }" : "=r"(a) : "l"(p));
    return a;
}
__device__ __forceinline__ uint32_t pack_h2(float2 v) {
    __half2 h = __float22half2_rn(v);
    return *reinterpret_cast<uint32_t*>(&h);
}
__device__ __forceinline__ uint32_t h2bits(float lo, float hi) {
    __half2 h = __halves2half2(__float2half_rn(lo), __float2half_rn(hi));
    return *reinterpret_cast<uint32_t*>(&h);
}

#define CP_ASYNC16(dst, src) \
    asm volatile("cp.async.cg.shared.global [%0], [%1], 16;" :: "r"(dst), "l"(src) : "memory")
#define CP_COMMIT()  asm volatile("cp.async.commit_group;" ::: "memory")
#define CP_WAIT(n)   asm volatile("cp.async.wait_group %0;" :: "n"(n) : "memory")

#define MMA_F16(d, a, b0, b1) \
    asm volatile("mma.sync.aligned.m16n8k16.row.col.f32.f16.f16.f32 " \
        "{%0,%1,%2,%3}, {%4,%5,%6,%7}, {%8,%9}, {%0,%1,%2,%3};" \
        : "+f"((d)[0]), "+f"((d)[1]), "+f"((d)[2]), "+f"((d)[3]) \
        : "r"((a)[0]), "r"((a)[1]), "r"((a)[2]), "r"((a)[3]), "r"(b0), "r"(b1))

// ---------------------------------------------------------------------------
// Prep: pack W into m16n8k16 B-fragment order, fp16 hi + scaled-residual lo.
// f = c*512 + nt*64 + ks*32 + lane
// e = nt*8 + lane/4, k0 = c*32 + ks*16 + (lane%4)*2
// ---------------------------------------------------------------------------
__global__ void w_pack_kernel(const float* __restrict__ w)
{
    int f = blockIdx.x * blockDim.x + threadIdx.x;   // 0..32767
    if (f == 0) g_ticket = 0;                        // reset per replay
    int lane = f & 31;
    int ks   = (f >> 5) & 1;
    int nt   = (f >> 6) & 7;
    int c    = f >> 9;
    int e  = nt * 8 + (lane >> 2);
    int k0 = c * 32 + ks * 16 + (lane & 3) * 2;

    float w00 = w[e * DDIM + k0],     w01 = w[e * DDIM + k0 + 1];
    float w08 = w[e * DDIM + k0 + 8], w09 = w[e * DDIM + k0 + 9];

    float h00 = __half2float(__float2half_rn(w00));
    float h01 = __half2float(__float2half_rn(w01));
    float h08 = __half2float(__float2half_rn(w08));
    float h09 = __half2float(__float2half_rn(w09));

    uint4 v;
    v.x = h2bits(h00, h01);                                   // b0 hi
    v.y = h2bits(h08, h09);                                   // b1 hi
    v.z = h2bits((w00 - h00) * RSCALE, (w01 - h01) * RSCALE); // b0 lo*4096
    v.w = h2bits((w08 - h08) * RSCALE, (w09 - h09) * RSCALE); // b1 lo*4096
    g_wpk[f] = v;
}

// ---------------------------------------------------------------------------
// Main fused kernel: 8 warps = 4 m-tiles x 2 k-steps, pipelined fragments
// ---------------------------------------------------------------------------
__global__ __launch_bounds__(256, 2)
void moe_gate_kernel(const float* __restrict__ x, float* __restrict__ out)
{
    extern __shared__ char smem[];
    const uint32_t sb = smem_u32(smem);
    const int tid  = threadIdx.x;
    const int warp = tid >> 5;
    const int lane = tid & 31;
    const int wm   = warp & 3;       // m-tile (16 rows)
    const int kh   = warp >> 2;      // k-step of the 32-wide chunk (0 or 1)
    const int m0   = blockIdx.x * M_CTA;

    __shared__ int s_cnt[NEXP];
    __shared__ int s_last;
    if (tid < NEXP) s_cnt[tid] = 0;

    float accm[8][4], accc[8][4];
#pragma unroll
    for (int nt = 0; nt < 8; nt++)
#pragma unroll
        for (int i = 0; i < 4; i++) { accm[nt][i] = 0.0f; accc[nt][i] = 0.0f; }

    auto stage = [&](int c, int s) {
        const uint32_t xd = sb + s * STG_SIZE;
        const uint32_t wd = xd + XS_BYTES;
#pragma unroll
        for (int i = 0; i < 2; i++) {           // x: 512 float4 (64 rows x 32 cols)
            int f = i * 256 + tid;
            int row = f >> 3, q = f & 7;
            const float* src = x + (size_t)(m0 + row) * DDIM + c * 32 + q * 4;
            CP_ASYNC16(xd + (uint32_t)(row * (XS_STRIDE * 4) + q * 16), src);
        }
        const uint4* wsrc = g_wpk + c * 512;
#pragma unroll
        for (int i = 0; i < 2; i++) {           // w: 512 uint4
            int f = i * 256 + tid;
            CP_ASYNC16(wd + (uint32_t)(f * 16), wsrc + f);
        }
        CP_COMMIT();
    };

    const int r0 = wm * 16 + (lane >> 2);
    const int k0 = kh * 16 + (lane & 3) * 2;    // this warp's fixed k-step cols

    uint32_t ah[4], al[4];                      // fragments for current chunk
    float2 xr0, xr1, xr2, xr3;                  // raw x for next chunk

    auto load_xraw = [&](int slot) {
        const float* xsb = reinterpret_cast<const float*>(smem + slot * STG_SIZE);
        xr0 = *reinterpret_cast<const float2*>(&xsb[r0 * XS_STRIDE + k0]);
        xr1 = *reinterpret_cast<const float2*>(&xsb[(r0 + 8) * XS_STRIDE + k0]);
        xr2 = *reinterpret_cast<const float2*>(&xsb[r0 * XS_STRIDE + k0 + 8]);
        xr3 = *reinterpret_cast<const float2*>(&xsb[(r0 + 8) * XS_STRIDE + k0 + 8]);
    };
    auto cvt_frag = [&]() {
        ah[0] = pack_h2(xr0); ah[1] = pack_h2(xr1);
        ah[2] = pack_h2(xr2); ah[3] = pack_h2(xr3);
        __half2 h0 = *reinterpret_cast<__half2*>(&ah[0]);
        __half2 h1 = *reinterpret_cast<__half2*>(&ah[1]);
        __half2 h2 = *reinterpret_cast<__half2*>(&ah[2]);
        __half2 h3 = *reinterpret_cast<__half2*>(&ah[3]);
        al[0] = pack_h2(make_float2((xr0.x - __low2float(h0)) * RSCALE,
                                    (xr0.y - __high2float(h0)) * RSCALE));
        al[1] = pack_h2(make_float2((xr1.x - __low2float(h1)) * RSCALE,
                                    (xr1.y - __high2float(h1)) * RSCALE));
        al[2] = pack_h2(make_float2((xr2.x - __low2float(h2)) * RSCALE,
                                    (xr2.y - __high2float(h2)) * RSCALE));
        al[3] = pack_h2(make_float2((xr3.x - __low2float(h3)) * RSCALE,
                                    (xr3.y - __high2float(h3)) * RSCALE));
    };
    auto mma_chunk = [&](int slot) {
        const uint4* wsb = reinterpret_cast<const uint4*>(smem + slot * STG_SIZE + XS_BYTES);
#pragma unroll
        for (int h = 0; h < 2; h++) {
            uint4 bq[4];
#pragma unroll
            for (int j = 0; j < 4; j++)
                bq[j] = wsb[(h * 4 + j) * 64 + kh * 32 + lane];
#pragma unroll
            for (int j = 0; j < 4; j++) MMA_F16(accm[h * 4 + j], ah, bq[j].x, bq[j].y);
#pragma unroll
            for (int j = 0; j < 4; j++) MMA_F16(accc[h * 4 + j], ah, bq[j].z, bq[j].w);
#pragma unroll
            for (int j = 0; j < 4; j++) MMA_F16(accc[h * 4 + j], al, bq[j].x, bq[j].y);
        }
    };

    // prologue: fill 4 stages, prepare fragments for chunk 0
    stage(0, 0); stage(1, 1); stage(2, 2); stage(3, 3);
    CP_WAIT(3);                     // chunk 0 resident
    __syncthreads();                // visible to all threads
    load_xraw(0);
    cvt_frag();

    for (int c = 0; c < NCHUNK; c += 2) {
        CP_WAIT(1);                 // chunks c, c+1, c+2 resident
        __syncthreads();
        if (c + 4 < NCHUNK) stage(c + 4, (c + 4) % NSTAGE);
        if (c + 5 < NCHUNK) stage(c + 5, (c + 5) % NSTAGE);

        // --- chunk c: prefetch x(c+1), MMA(c), cvt -> frag(c+1) ---
        load_xraw((c + 1) % NSTAGE);
        mma_chunk(c % NSTAGE);
        cvt_frag();

        // --- chunk c+1: prefetch x(c+2), MMA(c+1), cvt -> frag(c+2) ---
        if (c + 2 < NCHUNK) load_xraw((c + 2) % NSTAGE);
        mma_chunk((c + 1) % NSTAGE);
        if (c + 2 < NCHUNK) cvt_frag();
    }
    __syncthreads();

    // ---- dump per-kstep partial logits: kstep kh -> rows [kh*64, kh*64+64) ----
    float* sc = reinterpret_cast<float*>(smem);
    {
        const int col = (lane & 3) * 2;
        const int rb  = kh * M_CTA + r0;
#pragma unroll
        for (int nt = 0; nt < 8; nt++) {
            const int cc = nt * 8 + col;
            float l0 = accm[nt][0] + accc[nt][0] * INV_RS;
            float l1 = accm[nt][1] + accc[nt][1] * INV_RS;
            float l2 = accm[nt][2] + accc[nt][2] * INV_RS;
            float l3 = accm[nt][3] + accc[nt][3] * INV_RS;
            *reinterpret_cast<float2*>(&sc[rb * SC_STRIDE + cc])       = make_float2(l0, l1);
            *reinterpret_cast<float2*>(&sc[(rb + 8) * SC_STRIDE + cc]) = make_float2(l2, l3);
        }
    }
    __syncthreads();

    // ---- per-token: combine k-halves, top-2, softmax, outputs ----
    if (tid < M_CTA) {
        float* row0 = &sc[tid * SC_STRIDE];
        const float* row1 = &sc[(M_CTA + tid) * SC_STRIDE];
        float v1 = -3.4e38f, v2 = -3.4e38f;
        int i1 = 0, i2 = 0;
#pragma unroll 8
        for (int e = 0; e < NEXP; e++) {
            float l = row0[e] + row1[e];
            row0[e] = l;
            if (l > v1)      { v2 = v1; i2 = i1; v1 = l; i1 = e; }
            else if (l > v2) { v2 = l; i2 = e; }
        }
        float denom = 0.0f;
#pragma unroll 8
        for (int e = 0; e < NEXP; e++) {
            float ex = expf(row0[e] - v1);
            row0[e] = ex;
            denom += ex;
        }
        const float inv = 1.0f / denom;
#pragma unroll 8
        for (int e = 0; e < NEXP; e++) row0[e] *= inv;

        const float s1 = row0[i1], s2 = row0[i2];
        const float wsum = s1 + s2 + 1e-20f;
        const int g = m0 + tid;
        out[2 * g + 0] = (float)i1;
        out[2 * g + 1] = (float)i2;
        out[2 * N_TOKENS + 2 * g + 0] = s1 / wsum;
        out[2 * N_TOKENS + 2 * g + 1] = s2 / wsum;

        atomicAdd(&s_cnt[i1], 1);
        atomicAdd(&s_cnt[i2], 1);
    }
    __syncthreads();

    // ---- per-CTA deterministic aux partials (colsum over prob rows 0..63) ----
    if (tid < NEXP) {
        float ss = 0.0f;
#pragma unroll 8
        for (int t = 0; t < M_CTA; t++) ss += sc[t * SC_STRIDE + tid];
        g_sum[blockIdx.x * NEXP + tid] = ss;
        g_cnt[blockIdx.x * NEXP + tid] = (float)s_cnt[tid];
    }

    // ---- last-CTA final reduction (deterministic order) ----
    __threadfence();
    __syncthreads();
    if (tid == 0) {
        unsigned t = atomicAdd(&g_ticket, 1u);
        s_last = (t == NCTA - 1) ? 1 : 0;
    }
    __syncthreads();
    if (s_last) {
        float* red = reinterpret_cast<float*>(smem);   // reuse
        const int b = tid >> 6;          // batch 0..3
        const int e = tid & 63;
        float cnt = 0.0f, ss = 0.0f;
        const int base = b * CTA_PER_BATCH;
        for (int cc = 0; cc < CTA_PER_BATCH; cc++) {
            cnt += g_cnt[(base + cc) * NEXP + e];
            ss  += g_sum[(base + cc) * NEXP + e];
        }
        float ce = cnt / ((float)S_LEN * 2.0f / (float)NEXP);
        float ms = ss / (float)S_LEN;
        red[tid] = ce * ms;
        __syncthreads();
        for (int s = 128; s > 0; s >>= 1) {
            if (tid < s) red[tid] += red[tid + s];
            __syncthreads();
        }
        if (tid == 0)
            out[4 * N_TOKENS] = red[0] * 0.01f / (float)NBATCH;
    }
}

// ---------------------------------------------------------------------------
extern "C" void kernel_launch(void* const* d_in, const int* in_sizes, int n_in,
                              void* d_out, int out_size)
{
    const float* x = (const float*)d_in[0];
    const float* w = (const float*)d_in[1];
    float* out = (float*)d_out;

    cudaFuncSetAttribute(moe_gate_kernel,
                         cudaFuncAttributeMaxDynamicSharedMemorySize, SMEM_BYTES);

    w_pack_kernel<<<128, 256>>>(w);
    moe_gate_kernel<<<NCTA, 256, SMEM_BYTES>>>(x, out);
}

// round 13
// speedup vs baseline: 1.1812x; 1.1812x over previous
#include <cuda_runtime.h>
#include <cuda_fp16.h>
#include <cstdint>

// ============================================================================
// MoEGate via mma.sync m16n8k16 fp16 2-term split (3 passes, scaled residuals)
// Round 13: NO smem pipeline. Direct LDG -> registers -> MMA.
//   x streamed from DRAM (no reuse exists), W fragments from L2 (512KB resident)
//   8 independent warps (4m x 2k), no mainloop barriers -> no convoy
// out fp32: [0,32768) indices, [32768,65536) weights, [65536] aux_loss
// ============================================================================

#define N_TOKENS 16384
#define DDIM     2048
#define NEXP     64
#define M_CTA    64
#define NCTA     (N_TOKENS / M_CTA)   // 256
#define NCHUNK   (DDIM / 32)          // 64 chunks of K=32
#define S_LEN    4096
#define NBATCH   4
#define CTA_PER_BATCH (NCTA / NBATCH) // 64
#define RSCALE   4096.0f
#define INV_RS   (1.0f / 4096.0f)
#define SC_STRIDE 66

// device scratch
__device__ uint4    g_wpk[NCHUNK * 512];      // fragment-packed W (h1 | h2*4096)
__device__ float    g_cnt[NCTA * NEXP];
__device__ float    g_sum[NCTA * NEXP];
__device__ unsigned g_ticket;

// ---------------------------------------------------------------------------
__device__ __forceinline__ uint32_t pack_h2(float2 v) {
    __half2 h = __float22half2_rn(v);
    return *reinterpret_cast<uint32_t*>(&h);
}
__device__ __forceinline__ uint32_t h2bits(float lo, float hi) {
    __half2 h = __halves2half2(__float2half_rn(lo), __float2half_rn(hi));
    return *reinterpret_cast<uint32_t*>(&h);
}

#define MMA_F16(d, a, b0, b1) \
    asm volatile("mma.sync.aligned.m16n8k16.row.col.f32.f16.f16.f32 " \
        "{%0,%1,%2,%3}, {%4,%5,%6,%7}, {%8,%9}, {%0,%1,%2,%3};" \
        : "+f"((d)[0]), "+f"((d)[1]), "+f"((d)[2]), "+f"((d)[3]) \
        : "r"((a)[0]), "r"((a)[1]), "r"((a)[2]), "r"((a)[3]), "r"(b0), "r"(b1))

// ---------------------------------------------------------------------------
// Prep: pack W into m16n8k16 B-fragment order, fp16 hi + scaled-residual lo.
// f = c*512 + nt*64 + ks*32 + lane
// e = nt*8 + lane/4, k0 = c*32 + ks*16 + (lane%4)*2
// ---------------------------------------------------------------------------
__global__ void w_pack_kernel(const float* __restrict__ w)
{
    int f = blockIdx.x * blockDim.x + threadIdx.x;   // 0..32767
    if (f == 0) g_ticket = 0;                        // reset per replay
    int lane = f & 31;
    int ks   = (f >> 5) & 1;
    int nt   = (f >> 6) & 7;
    int c    = f >> 9;
    int e  = nt * 8 + (lane >> 2);
    int k0 = c * 32 + ks * 16 + (lane & 3) * 2;

    float w00 = w[e * DDIM + k0],     w01 = w[e * DDIM + k0 + 1];
    float w08 = w[e * DDIM + k0 + 8], w09 = w[e * DDIM + k0 + 9];

    float h00 = __half2float(__float2half_rn(w00));
    float h01 = __half2float(__float2half_rn(w01));
    float h08 = __half2float(__float2half_rn(w08));
    float h09 = __half2float(__float2half_rn(w09));

    uint4 v;
    v.x = h2bits(h00, h01);                                   // b0 hi
    v.y = h2bits(h08, h09);                                   // b1 hi
    v.z = h2bits((w00 - h00) * RSCALE, (w01 - h01) * RSCALE); // b0 lo*4096
    v.w = h2bits((w08 - h08) * RSCALE, (w09 - h09) * RSCALE); // b1 lo*4096
    g_wpk[f] = v;
}

// ---------------------------------------------------------------------------
// Main fused kernel: 8 warps = 4 m-tiles x 2 k-steps, no smem mainloop
// ---------------------------------------------------------------------------
__global__ __launch_bounds__(256, 2)
void moe_gate_kernel(const float* __restrict__ x, float* __restrict__ out)
{
    __shared__ float sc[128 * SC_STRIDE];   // 33.8 KB: partial logits / probs
    __shared__ int   s_cnt[NEXP];
    __shared__ int   s_last;

    const int tid  = threadIdx.x;
    const int warp = tid >> 5;
    const int lane = tid & 31;
    const int wm   = warp & 3;       // m-tile (16 rows)
    const int kh   = warp >> 2;      // k-step of each 32-wide chunk (0 or 1)
    const int m0   = blockIdx.x * M_CTA;

    if (tid < NEXP) s_cnt[tid] = 0;

    float accm[8][4], accc[8][4];
#pragma unroll
    for (int nt = 0; nt < 8; nt++)
#pragma unroll
        for (int i = 0; i < 4; i++) { accm[nt][i] = 0.0f; accc[nt][i] = 0.0f; }

    // per-thread x addresses: rows r0, r0+8; cols c0, c0+8 (advance 32/chunk)
    const int r0 = wm * 16 + (lane >> 2);
    const int c0 = kh * 16 + (lane & 3) * 2;
    const float* xp = x + (size_t)(m0 + r0) * DDIM + c0;

    // W fragment pointer: + c*512 + (h*4+j)*64 + (kh*32 + lane)
    const uint4* wp = g_wpk + kh * 32 + lane;

    // prefetch x raw for chunk 0
    float2 xr0 = *reinterpret_cast<const float2*>(xp);
    float2 xr1 = *reinterpret_cast<const float2*>(xp + 8 * DDIM);
    float2 xr2 = *reinterpret_cast<const float2*>(xp + 8);
    float2 xr3 = *reinterpret_cast<const float2*>(xp + 8 * DDIM + 8);

    for (int c = 0; c < NCHUNK; c++) {
        // ---- W fragments for chunk c (L2-resident) ----
        const uint4* wc = wp + c * 512;
        uint4 bq[8];
#pragma unroll
        for (int j = 0; j < 8; j++) bq[j] = __ldg(wc + j * 64);

        // ---- prefetch x raw for chunk c+1 (DRAM stream) ----
        const int cn = (c + 1 < NCHUNK) ? (c + 1) : 0;   // last prefetch harmless
        const float* xq = xp + cn * 32;
        float2 xn0 = *reinterpret_cast<const float2*>(xq);
        float2 xn1 = *reinterpret_cast<const float2*>(xq + 8 * DDIM);
        float2 xn2 = *reinterpret_cast<const float2*>(xq + 8);
        float2 xn3 = *reinterpret_cast<const float2*>(xq + 8 * DDIM + 8);

        // ---- convert current x raw to fp16 hi/lo fragments ----
        uint32_t ah[4], al[4];
        ah[0] = pack_h2(xr0); ah[1] = pack_h2(xr1);
        ah[2] = pack_h2(xr2); ah[3] = pack_h2(xr3);
        {
            __half2 h0 = *reinterpret_cast<__half2*>(&ah[0]);
            __half2 h1 = *reinterpret_cast<__half2*>(&ah[1]);
            __half2 h2 = *reinterpret_cast<__half2*>(&ah[2]);
            __half2 h3 = *reinterpret_cast<__half2*>(&ah[3]);
            al[0] = pack_h2(make_float2((xr0.x - __low2float(h0)) * RSCALE,
                                        (xr0.y - __high2float(h0)) * RSCALE));
            al[1] = pack_h2(make_float2((xr1.x - __low2float(h1)) * RSCALE,
                                        (xr1.y - __high2float(h1)) * RSCALE));
            al[2] = pack_h2(make_float2((xr2.x - __low2float(h2)) * RSCALE,
                                        (xr2.y - __high2float(h2)) * RSCALE));
            al[3] = pack_h2(make_float2((xr3.x - __low2float(h3)) * RSCALE,
                                        (xr3.y - __high2float(h3)) * RSCALE));
        }

        // ---- 24 MMAs, pass-major (RAW distance 8) ----
#pragma unroll
        for (int j = 0; j < 8; j++) MMA_F16(accm[j], ah, bq[j].x, bq[j].y);
#pragma unroll
        for (int j = 0; j < 8; j++) MMA_F16(accc[j], ah, bq[j].z, bq[j].w);
#pragma unroll
        for (int j = 0; j < 8; j++) MMA_F16(accc[j], al, bq[j].x, bq[j].y);

        xr0 = xn0; xr1 = xn1; xr2 = xn2; xr3 = xn3;
    }

    // ---- dump per-kstep partial logits: kstep kh -> rows [kh*64, kh*64+64) ----
    {
        const int col = (lane & 3) * 2;
        const int rb  = kh * M_CTA + r0;
#pragma unroll
        for (int nt = 0; nt < 8; nt++) {
            const int cc = nt * 8 + col;
            float l0 = accm[nt][0] + accc[nt][0] * INV_RS;
            float l1 = accm[nt][1] + accc[nt][1] * INV_RS;
            float l2 = accm[nt][2] + accc[nt][2] * INV_RS;
            float l3 = accm[nt][3] + accc[nt][3] * INV_RS;
            *reinterpret_cast<float2*>(&sc[rb * SC_STRIDE + cc])       = make_float2(l0, l1);
            *reinterpret_cast<float2*>(&sc[(rb + 8) * SC_STRIDE + cc]) = make_float2(l2, l3);
        }
    }
    __syncthreads();

    // ---- per-token: combine k-halves, top-2, softmax, outputs ----
    if (tid < M_CTA) {
        float* row0 = &sc[tid * SC_STRIDE];
        const float* row1 = &sc[(M_CTA + tid) * SC_STRIDE];
        float v1 = -3.4e38f, v2 = -3.4e38f;
        int i1 = 0, i2 = 0;
#pragma unroll 8
        for (int e = 0; e < NEXP; e++) {
            float l = row0[e] + row1[e];
            row0[e] = l;
            if (l > v1)      { v2 = v1; i2 = i1; v1 = l; i1 = e; }
            else if (l > v2) { v2 = l; i2 = e; }
        }
        float denom = 0.0f;
#pragma unroll 8
        for (int e = 0; e < NEXP; e++) {
            float ex = expf(row0[e] - v1);
            row0[e] = ex;
            denom += ex;
        }
        const float inv = 1.0f / denom;
#pragma unroll 8
        for (int e = 0; e < NEXP; e++) row0[e] *= inv;

        const float s1 = row0[i1], s2 = row0[i2];
        const float wsum = s1 + s2 + 1e-20f;
        const int g = m0 + tid;
        out[2 * g + 0] = (float)i1;
        out[2 * g + 1] = (float)i2;
        out[2 * N_TOKENS + 2 * g + 0] = s1 / wsum;
        out[2 * N_TOKENS + 2 * g + 1] = s2 / wsum;

        atomicAdd(&s_cnt[i1], 1);
        atomicAdd(&s_cnt[i2], 1);
    }
    __syncthreads();

    // ---- per-CTA deterministic aux partials (colsum over prob rows 0..63) ----
    if (tid < NEXP) {
        float ss = 0.0f;
#pragma unroll 8
        for (int t = 0; t < M_CTA; t++) ss += sc[t * SC_STRIDE + tid];
        g_sum[blockIdx.x * NEXP + tid] = ss;
        g_cnt[blockIdx.x * NEXP + tid] = (float)s_cnt[tid];
    }

    // ---- last-CTA final reduction (deterministic order) ----
    __threadfence();
    __syncthreads();
    if (tid == 0) {
        unsigned t = atomicAdd(&g_ticket, 1u);
        s_last = (t == NCTA - 1) ? 1 : 0;
    }
    __syncthreads();
    if (s_last) {
        float* red = sc;                 // reuse
        const int b = tid >> 6;          // batch 0..3
        const int e = tid & 63;
        float cnt = 0.0f, ss = 0.0f;
        const int base = b * CTA_PER_BATCH;
        for (int cc = 0; cc < CTA_PER_BATCH; cc++) {
            cnt += g_cnt[(base + cc) * NEXP + e];
            ss  += g_sum[(base + cc) * NEXP + e];
        }
        float ce = cnt / ((float)S_LEN * 2.0f / (float)NEXP);
        float ms = ss / (float)S_LEN;
        red[tid] = ce * ms;
        __syncthreads();
        for (int s = 128; s > 0; s >>= 1) {
            if (tid < s) red[tid] += red[tid + s];
            __syncthreads();
        }
        if (tid == 0)
            out[4 * N_TOKENS] = red[0] * 0.01f / (float)NBATCH;
    }
}

// ---------------------------------------------------------------------------
extern "C" void kernel_launch(void* const* d_in, const int* in_sizes, int n_in,
                              void* d_out, int out_size)
{
    const float* x = (const float*)d_in[0];
    const float* w = (const float*)d_in[1];
    float* out = (float*)d_out;

    w_pack_kernel<<<128, 256>>>(w);
    moe_gate_kernel<<<NCTA, 256>>>(x, out);
}